// round 9
// baseline (speedup 1.0000x reference)
#include <cuda_runtime.h>
#include <cstdint>
#include <cstddef>

typedef unsigned long long ull;

#define BB 64
#define TT 1024
#define DD 256
#define UU 256
#define MM (BB*TT)          // 65536 rows for the input projection

// Scan weight split: KREG k-rows in registers, KS k-rows streamed from SMEM
#define KREG 160
#define NWU  (KREG/2)       // 80 packed (k-pair) ull per thread in regs
#define KS   (UU-KREG)      // 96
#define NWS  (KS/2)         // 48 packed rows in dynamic SMEM (96 KB)

// ---------------- packed f32x2 helpers ----------------
__device__ __forceinline__ ull fma2(ull a, ull b, ull c){
    ull d;
    asm("fma.rn.f32x2 %0, %1, %2, %3;" : "=l"(d) : "l"(a), "l"(b), "l"(c));
    return d;
}
__device__ __forceinline__ float2 unpack2(ull a){
    float2 r;
    asm("mov.b64 {%0, %1}, %2;" : "=f"(r.x), "=f"(r.y) : "l"(a));
    return r;
}
__device__ __forceinline__ ull pack2(float lo, float hi){
    ull p;
    asm("mov.b64 %0, {%1, %2};" : "=l"(p) : "f"(lo), "f"(hi));
    return p;
}
__device__ __forceinline__ ull wload(const float* W, int k, int u){
    return pack2(W[(size_t)k*UU + u], W[(size_t)(k+1)*UU + u]);
}

// fast tanh: branchless, 2 MUFU ops. |x| is bounded (~10) in this model;
// clamp keeps exp finite for any input.
__device__ __forceinline__ float fast_tanh(float x){
    float xc = fminf(fmaxf(x, -15.f), 15.f);
    float e  = __expf(2.f*xc);
    return __fdividef(e - 1.f, e + 1.f);
}

// ---------------- input projection GEMM (unchanged, proven) ----------------
#define GR 32   // rows per block

__device__ __forceinline__ void gemm_chunk(const float* xs, int cc, const ull* w, ull* acc){
    #pragma unroll
    for (int r = 0; r < GR; r++){
        const ulonglong2* xr = reinterpret_cast<const ulonglong2*>(xs + r*UU) + cc*4;
        #pragma unroll
        for (int j = 0; j < 4; j++){
            ulonglong2 xx = xr[j];
            acc[r] = fma2(xx.x, w[2*j],   acc[r]);
            acc[r] = fma2(xx.y, w[2*j+1], acc[r]);
        }
    }
}

__global__ void __launch_bounds__(256,1) gemm_kernel(const float* __restrict__ X,
                                                     const float* __restrict__ Wxh,
                                                     const float* __restrict__ bh,
                                                     float* __restrict__ out){
    __shared__ __align__(16) float xs[GR*UU];
    const int u    = threadIdx.x;
    const int row0 = blockIdx.x * GR;

    {
        const float4* Xv = reinterpret_cast<const float4*>(X + (size_t)row0*UU);
        float4* sv = reinterpret_cast<float4*>(xs);
        #pragma unroll
        for (int i = 0; i < (GR*UU/4)/256; i++)
            sv[threadIdx.x + i*256] = Xv[threadIdx.x + i*256];
    }
    float bias = bh[u];
    __syncthreads();

    ull acc[GR];
    #pragma unroll
    for (int r = 0; r < GR; r++) acc[r] = 0ULL;

    ull wcur[8], wnxt[8];
    #pragma unroll
    for (int j = 0; j < 8; j++) wcur[j] = wload(Wxh, 2*j, u);

    #pragma unroll 1
    for (int c = 0; c < 16; c += 2){
        #pragma unroll
        for (int j = 0; j < 8; j++) wnxt[j] = wload(Wxh, 2*((c+1)*8 + j), u);
        gemm_chunk(xs, c, wcur, acc);
        if (c + 2 < 16){
            #pragma unroll
            for (int j = 0; j < 8; j++) wcur[j] = wload(Wxh, 2*((c+2)*8 + j), u);
        }
        gemm_chunk(xs, c+1, wnxt, acc);
    }

    #pragma unroll
    for (int r = 0; r < GR; r++){
        float2 v = unpack2(acc[r]);
        out[(size_t)(row0 + r)*UU + u] = v.x + v.y + bias;   // xW pre-activation
    }
}

// ---------------- sequential scan: one CTA per batch row, single BAR/step ----
// KREG=160 rows register-resident (160 regs), KS=96 rows streamed from SMEM.
// ~35+ regs of scheduling headroom lets ptxas hoist/pipeline the LDS loads.
extern __shared__ ull ws[];   // NWS*UU packed rows (98304 bytes)

__global__ void __launch_bounds__(256,1) scan_kernel(const float* __restrict__ Whh,
                                                     float* __restrict__ out){
    __shared__ __align__(16) float hbuf[2][UU];
    const int u = threadIdx.x;
    const int b = blockIdx.x;

    // register-resident W_hh rows (k in [0, KREG)), packed inline from fp32
    ull w[NWU];
    #pragma unroll
    for (int j = 0; j < NWU; j++) w[j] = wload(Whh, 2*j, u);

    // SMEM-resident W_hh rows (k in [KREG, 256))
    #pragma unroll
    for (int i = 0; i < NWS; i++) ws[i*UU + u] = wload(Whh, KREG + 2*i, u);

    hbuf[0][u] = 0.f;
    hbuf[1][u] = 0.f;
    __syncthreads();

    float* row = out + ((size_t)b*TT)*UU + u;   // holds xw on entry, h on exit

    int p = 0;
    #pragma unroll 1
    for (int t = 0; t < TT; t++){
        float xw = row[0];           // pre-activation (L2-resident), hidden under step
        ull a0 = 0ULL, a1 = 0ULL;
        const ulonglong2* hv = reinterpret_cast<const ulonglong2*>(hbuf[p]);

        // register-weight part: 80 packed FMA2s (two independent chains)
        #pragma unroll
        for (int j = 0; j < NWU/2; j++){
            ulonglong2 hh = hv[j];                    // broadcast LDS.128: h[4j..4j+3]
            a0 = fma2(hh.x, w[2*j],   a0);
            a1 = fma2(hh.y, w[2*j+1], a1);
        }
        // SMEM-streamed weight part: 48 packed FMA2s
        #pragma unroll
        for (int j = 0; j < NWS/2; j++){
            ulonglong2 hh = hv[NWU/2 + j];
            a0 = fma2(hh.x, ws[(2*j)*UU + u],   a0);
            a1 = fma2(hh.y, ws[(2*j+1)*UU + u], a1);
        }

        float2 v0 = unpack2(a0), v1 = unpack2(a1);
        float h = fast_tanh((v0.x + v1.x) + (v0.y + v1.y) + xw);

        hbuf[p^1][u] = h;
        row[0] = h;                  // overwrite with h_t
        __syncthreads();
        p ^= 1;
        row += UU;
    }
}

// ---------------- launch ----------------
extern "C" void kernel_launch(void* const* d_in, const int* in_sizes, int n_in,
                              void* d_out, int out_size){
    int idx_inputs = -1, idx_b = -1;
    int widx[2] = {-1, -1}; int nw = 0;
    for (int i = 0; i < n_in; i++){
        long long sz = in_sizes[i];
        if      (sz == (long long)MM*DD || sz == (long long)MM*DD*4) idx_inputs = i;
        else if (sz == UU || sz == UU*4)                             idx_b = i;
        else if (nw < 2)                                             widx[nw++] = i;
    }

    const float *X, *bh, *Wxh, *Whh;
    if (idx_inputs >= 0 && idx_b >= 0 && nw == 2){
        X  = (const float*)d_in[idx_inputs];
        bh = (const float*)d_in[idx_b];
        if (idx_inputs < widx[0]){
            Wxh = (const float*)d_in[widx[0]];
            Whh = (const float*)d_in[widx[1]];
        } else {
            Whh = (const float*)d_in[widx[0]];
            Wxh = (const float*)d_in[widx[1]];
        }
    } else {
        X   = (const float*)d_in[0];
        Wxh = (const float*)d_in[1];
        Whh = (const float*)d_in[2];
        bh  = (const float*)d_in[3];
    }
    float* out = (float*)d_out;                 // [64,1024,256] fp32

    cudaFuncSetAttribute(scan_kernel, cudaFuncAttributeMaxDynamicSharedMemorySize, NWS*UU*8);

    gemm_kernel<<<MM/GR, 256>>>(X, Wxh, bh, out);
    scan_kernel<<<BB, 256, NWS*UU*8>>>(Whh, out);
}

// round 10
// speedup vs baseline: 1.2578x; 1.2578x over previous
#include <cuda_runtime.h>
#include <cstdint>
#include <cstddef>

typedef unsigned long long ull;

#define BB 64
#define TT 1024
#define DD 256
#define UU 256
#define MM (BB*TT)          // 65536 rows for the input projection

// ---- scan k-split config: 512 threads = 2 k-halves x 256 u ----
// per-thread k range = 128 values = 64 packed pairs:
//   40 pairs register-resident, 24 pairs streamed from SMEM
#define PREG 40
#define PSTR 24            // streamed pairs per thread -> ws = 2*24*256*8 = 96 KB

// ---------------- packed f32x2 helpers ----------------
__device__ __forceinline__ ull fma2(ull a, ull b, ull c){
    ull d;
    asm("fma.rn.f32x2 %0, %1, %2, %3;" : "=l"(d) : "l"(a), "l"(b), "l"(c));
    return d;
}
__device__ __forceinline__ float2 unpack2(ull a){
    float2 r;
    asm("mov.b64 {%0, %1}, %2;" : "=f"(r.x), "=f"(r.y) : "l"(a));
    return r;
}
__device__ __forceinline__ ull pack2(float lo, float hi){
    ull p;
    asm("mov.b64 %0, {%1, %2};" : "=l"(p) : "f"(lo), "f"(hi));
    return p;
}
__device__ __forceinline__ ull wload(const float* W, int k, int u){
    return pack2(W[(size_t)k*UU + u], W[(size_t)(k+1)*UU + u]);
}

// fast tanh: branchless, 2 MUFU ops; clamp keeps exp finite for any input
__device__ __forceinline__ float fast_tanh(float x){
    float xc = fminf(fmaxf(x, -15.f), 15.f);
    float e  = __expf(2.f*xc);
    return __fdividef(e - 1.f, e + 1.f);
}

// ---------------- input projection GEMM (unchanged, proven) ----------------
#define GR 32   // rows per block

__device__ __forceinline__ void gemm_chunk(const float* xs, int cc, const ull* w, ull* acc){
    #pragma unroll
    for (int r = 0; r < GR; r++){
        const ulonglong2* xr = reinterpret_cast<const ulonglong2*>(xs + r*UU) + cc*4;
        #pragma unroll
        for (int j = 0; j < 4; j++){
            ulonglong2 xx = xr[j];
            acc[r] = fma2(xx.x, w[2*j],   acc[r]);
            acc[r] = fma2(xx.y, w[2*j+1], acc[r]);
        }
    }
}

__global__ void __launch_bounds__(256,1) gemm_kernel(const float* __restrict__ X,
                                                     const float* __restrict__ Wxh,
                                                     const float* __restrict__ bh,
                                                     float* __restrict__ out){
    __shared__ __align__(16) float xs[GR*UU];
    const int u    = threadIdx.x;
    const int row0 = blockIdx.x * GR;

    {
        const float4* Xv = reinterpret_cast<const float4*>(X + (size_t)row0*UU);
        float4* sv = reinterpret_cast<float4*>(xs);
        #pragma unroll
        for (int i = 0; i < (GR*UU/4)/256; i++)
            sv[threadIdx.x + i*256] = Xv[threadIdx.x + i*256];
    }
    float bias = bh[u];
    __syncthreads();

    ull acc[GR];
    #pragma unroll
    for (int r = 0; r < GR; r++) acc[r] = 0ULL;

    ull wcur[8], wnxt[8];
    #pragma unroll
    for (int j = 0; j < 8; j++) wcur[j] = wload(Wxh, 2*j, u);

    #pragma unroll 1
    for (int c = 0; c < 16; c += 2){
        #pragma unroll
        for (int j = 0; j < 8; j++) wnxt[j] = wload(Wxh, 2*((c+1)*8 + j), u);
        gemm_chunk(xs, c, wcur, acc);
        if (c + 2 < 16){
            #pragma unroll
            for (int j = 0; j < 8; j++) wcur[j] = wload(Wxh, 2*((c+2)*8 + j), u);
        }
        gemm_chunk(xs, c+1, wnxt, acc);
    }

    #pragma unroll
    for (int r = 0; r < GR; r++){
        float2 v = unpack2(acc[r]);
        out[(size_t)(row0 + r)*UU + u] = v.x + v.y + bias;   // xW pre-activation
    }
}

// ---------------- sequential scan: 1 CTA/batch-row, 512 threads, 2-way k-split ----
// thread (u = t&255, kh = t>>8) covers k in [kh*128, kh*128+128) for column u.
// Weights: 40 pairs in regs + 24 pairs streamed (96 KB SMEM, conflict-free).
extern __shared__ ull ws[];   // [2*PSTR][UU] packed pairs (96 KB)

__global__ void __launch_bounds__(512,1) scan_kernel(const float* __restrict__ Whh,
                                                     float* __restrict__ out){
    __shared__ __align__(16) float hbuf[2][UU];
    __shared__ float redbuf[UU];
    const int t  = threadIdx.x;
    const int u  = t & 255;
    const int kh = t >> 8;                 // 0/1
    const int b  = blockIdx.x;
    const int kbase = kh*128;

    // register-resident pairs: k = kbase + 2j, j in [0, PREG)
    ull w[PREG];
    #pragma unroll
    for (int j = 0; j < PREG; j++) w[j] = wload(Whh, kbase + 2*j, u);

    // streamed pairs: k = kbase + 2*PREG + 2i, i in [0, PSTR)
    #pragma unroll
    for (int i = 0; i < PSTR; i++)
        ws[(kh*PSTR + i)*UU + u] = wload(Whh, kbase + 2*PREG + 2*i, u);

    if (t < UU){ hbuf[0][t] = 0.f; hbuf[1][t] = 0.f; }
    __syncthreads();

    float* row = out + ((size_t)b*TT)*UU + u;   // kh==0 threads own the output column

    int p = 0;
    #pragma unroll 1
    for (int tt = 0; tt < TT; tt++){
        float xw = (kh == 0) ? row[0] : 0.f;    // pre-activation (L2), hoisted early

        // h half for this thread: 128 floats = 16 LDS.128 (broadcast)
        const ulonglong2* hv = reinterpret_cast<const ulonglong2*>(&hbuf[p][kbase]);

        ull a0 = 0ULL, a1 = 0ULL;
        // register-weight part: 40 FMA2 (pairs j -> hv[i], i = j/2)
        #pragma unroll
        for (int i = 0; i < PREG/2; i++){
            ulonglong2 hh = hv[i];
            a0 = fma2(hh.x, w[2*i],   a0);
            a1 = fma2(hh.y, w[2*i+1], a1);
        }
        // streamed part: 24 FMA2
        #pragma unroll
        for (int i = 0; i < PSTR/2; i++){
            ulonglong2 hh = hv[PREG/2 + i];
            a0 = fma2(hh.x, ws[(kh*PSTR + 2*i)*UU + u],   a0);
            a1 = fma2(hh.y, ws[(kh*PSTR + 2*i+1)*UU + u], a1);
        }

        float2 v0 = unpack2(a0), v1 = unpack2(a1);
        float part = (v0.x + v0.y) + (v1.x + v1.y);

        if (kh == 1) redbuf[u] = part;
        __syncthreads();                         // partials ready

        if (kh == 0){
            float h = fast_tanh(part + redbuf[u] + xw);
            hbuf[p^1][u] = h;
            row[0] = h;
            row += UU;
        }
        __syncthreads();                         // next h visible to all
        p ^= 1;
    }
}

// ---------------- launch ----------------
extern "C" void kernel_launch(void* const* d_in, const int* in_sizes, int n_in,
                              void* d_out, int out_size){
    int idx_inputs = -1, idx_b = -1;
    int widx[2] = {-1, -1}; int nw = 0;
    for (int i = 0; i < n_in; i++){
        long long sz = in_sizes[i];
        if      (sz == (long long)MM*DD || sz == (long long)MM*DD*4) idx_inputs = i;
        else if (sz == UU || sz == UU*4)                             idx_b = i;
        else if (nw < 2)                                             widx[nw++] = i;
    }

    const float *X, *bh, *Wxh, *Whh;
    if (idx_inputs >= 0 && idx_b >= 0 && nw == 2){
        X  = (const float*)d_in[idx_inputs];
        bh = (const float*)d_in[idx_b];
        if (idx_inputs < widx[0]){
            Wxh = (const float*)d_in[widx[0]];
            Whh = (const float*)d_in[widx[1]];
        } else {
            Whh = (const float*)d_in[widx[0]];
            Wxh = (const float*)d_in[widx[1]];
        }
    } else {
        X   = (const float*)d_in[0];
        Wxh = (const float*)d_in[1];
        Whh = (const float*)d_in[2];
        bh  = (const float*)d_in[3];
    }
    float* out = (float*)d_out;                 // [64,1024,256] fp32

    const int WS_BYTES = 2*PSTR*UU*8;           // 96 KB
    cudaFuncSetAttribute(scan_kernel, cudaFuncAttributeMaxDynamicSharedMemorySize, WS_BYTES);

    gemm_kernel<<<MM/GR, 256>>>(X, Wxh, bh, out);
    scan_kernel<<<BB, 512, WS_BYTES>>>(Whh, out);
}